// round 13
// baseline (speedup 1.0000x reference)
#include <cuda_runtime.h>
#include <cuda_bf16.h>
#include <math.h>
#include <stdint.h>

typedef unsigned long long ull;

#define NE 80000
#define TT 2000
#define SS 12
#define HH 128
#define EB 64                      // electrons per CTA (MMA M)
#define MASK_COEF 1.2615662610f    // GAUSS_NORM / sqrt(0.1)

// smem word offsets
#define SW_AHI 0                   // 64 x 68 (bf16x2 k-pairs, padded stride); reused for h2-hi
#define SW_ALO (SW_AHI + EB*68)    // 4352; reused for h2-lo
#define SW_B2  (SW_ALO + EB*68)    // 8704
#define SW_B3  (SW_B2 + HH)        // 8832 (+16)
#define SW_RESP (SW_B3 + 16)       // 8848: 64 x 12 f32
#define SW_TOT (SW_RESP + EB*SS)   // 9616 words = 38464 B

// W2 fragments: [spB(2)][kk(8)][ntile(16)][lane(32)] -> (b0,b1)
__device__ ull g_Bfrag[2 * 8 * 16 * 32];
// W3 fragments: [spB(2)][kk(8)][ntile(2)][lane(32)]  (N=16: sensors 0..11 + pad)
__device__ ull g_W3frag[2 * 8 * 2 * 32];

__device__ __forceinline__ uint32_t bfpack(float a, float b) {
    __nv_bfloat162 t(__float2bfloat16(a), __float2bfloat16(b));
    return *(uint32_t*)&t;
}
__device__ __forceinline__ uint32_t smem_u32(const void* p) {
    uint32_t a;
    asm("{ .reg .u64 t; cvta.to.shared.u64 t, %1; cvt.u32.u64 %0, t; }" : "=r"(a) : "l"(p));
    return a;
}
__device__ __forceinline__ void ldsm4(uint32_t* r, uint32_t addr) {
    asm volatile("ldmatrix.sync.aligned.m8n8.x4.shared.b16 {%0,%1,%2,%3}, [%4];"
        : "=r"(r[0]), "=r"(r[1]), "=r"(r[2]), "=r"(r[3]) : "r"(addr));
}
__device__ __forceinline__ void mma16816(float* c, const uint32_t* a, uint32_t b0, uint32_t b1) {
    asm volatile(
        "mma.sync.aligned.m16n8k16.row.col.f32.bf16.bf16.f32 "
        "{%0,%1,%2,%3}, {%4,%5,%6,%7}, {%8,%9}, {%0,%1,%2,%3};"
        : "+f"(c[0]), "+f"(c[1]), "+f"(c[2]), "+f"(c[3])
        : "r"(a[0]), "r"(a[1]), "r"(a[2]), "r"(a[3]), "r"(b0), "r"(b1));
}

// one launch: zero output + pack W2 fragments + pack W3 fragments (R11-validated)
__global__ void prep_zero_kernel(const float* __restrict__ W2,
                                 const float* __restrict__ W3,
                                 float4* __restrict__ out4) {
    int idx = blockIdx.x * 256 + threadIdx.x;
    if (idx < 48000) out4[idx] = make_float4(0.f, 0.f, 0.f, 0.f);

    if (idx < 8192) {
        int lane  = idx & 31;
        int ntile = (idx >> 5) & 15;
        int kk    = (idx >> 9) & 7;
        int spB   = idx >> 12;
        int kp0 = kk * 8 + (lane & 3);
        int n   = ntile * 8 + (lane >> 2);
        float v0 = W2[(2 * kp0) * HH + n];
        float v1 = W2[(2 * kp0 + 1) * HH + n];
        float w0 = W2[(2 * (kp0 + 4)) * HH + n];
        float w1 = W2[(2 * (kp0 + 4) + 1) * HH + n];
        uint32_t b0, b1;
        if (spB == 0) { b0 = bfpack(v0, v1); b1 = bfpack(w0, w1); }
        else {
            b0 = bfpack(v0 - __bfloat162float(__float2bfloat16(v0)),
                        v1 - __bfloat162float(__float2bfloat16(v1)));
            b1 = bfpack(w0 - __bfloat162float(__float2bfloat16(w0)),
                        w1 - __bfloat162float(__float2bfloat16(w1)));
        }
        g_Bfrag[idx] = ((ull)b1 << 32) | (ull)b0;
    } else if (idx < 8192 + 1024) {
        int t = idx - 8192;
        int lane = t & 31;
        int nt   = (t >> 5) & 1;
        int kk   = (t >> 6) & 7;
        int spB  = t >> 9;
        int kp0 = kk * 8 + (lane & 3);
        int n   = nt * 8 + (lane >> 2);
        float v0 = 0.f, v1 = 0.f, w0 = 0.f, w1 = 0.f;
        if (n < SS) {
            v0 = W3[(2 * kp0) * SS + n];
            v1 = W3[(2 * kp0 + 1) * SS + n];
            w0 = W3[(2 * (kp0 + 4)) * SS + n];
            w1 = W3[(2 * (kp0 + 4) + 1) * SS + n];
        }
        uint32_t b0, b1;
        if (spB == 0) { b0 = bfpack(v0, v1); b1 = bfpack(w0, w1); }
        else {
            b0 = bfpack(v0 - __bfloat162float(__float2bfloat16(v0)),
                        v1 - __bfloat162float(__float2bfloat16(v1)));
            b1 = bfpack(w0 - __bfloat162float(__float2bfloat16(w0)),
                        w1 - __bfloat162float(__float2bfloat16(w1)));
        }
        g_W3frag[t] = ((ull)b1 << 32) | (ull)b0;
    }
}

__global__ __launch_bounds__(256, 3)
void fused_sensor_kernel(
    const float* __restrict__ de,    // (B,N,3)
    const float* __restrict__ mask,  // (B,N)
    const float* __restrict__ W1,    // (3,H)
    const float* __restrict__ b1,    // (H)
    const float* __restrict__ b2,    // (H)
    const float* __restrict__ b3,    // (S)
    float* __restrict__ out)         // (B,S,T)
{
    extern __shared__ uint32_t smw[];
    float* smf = (float*)smw;
    const uint32_t smb = smem_u32(smw);
    const int tid  = threadIdx.x;
    const int lane = tid & 31;
    const int wid  = tid >> 5;

    // ---- small biases to smem ----
    if (tid < HH) smf[SW_B2 + tid] = b2[tid];
    if (tid < SS) smf[SW_B3 + tid] = b3[tid];

    // ---- layer 1 -> A hi/lo (4 threads/electron, 32 h1 values each) ----
    const int el = tid >> 2;
    const int q  = tid & 3;
    const int eg = blockIdx.x * EB + el;
    const float x0 = de[3 * eg + 0];
    const float x1 = de[3 * eg + 1];
    const float x2 = de[3 * eg + 2];
    const float msk = mask[eg];
#pragma unroll 4
    for (int i4 = 0; i4 < 8; ++i4) {
        int k = q * 32 + i4 * 4;
        float4 wa = *(const float4*)&W1[k];
        float4 wb = *(const float4*)&W1[HH + k];
        float4 wc = *(const float4*)&W1[2 * HH + k];
        float4 bb = *(const float4*)&b1[k];
        float v0 = fmaxf(fmaf(x2, wc.x, fmaf(x1, wb.x, fmaf(x0, wa.x, bb.x))), 0.f);
        float v1 = fmaxf(fmaf(x2, wc.y, fmaf(x1, wb.y, fmaf(x0, wa.y, bb.y))), 0.f);
        float v2 = fmaxf(fmaf(x2, wc.z, fmaf(x1, wb.z, fmaf(x0, wa.z, bb.z))), 0.f);
        float v3 = fmaxf(fmaf(x2, wc.w, fmaf(x1, wb.w, fmaf(x0, wa.w, bb.w))), 0.f);
        int kp = k >> 1;
        smw[SW_AHI + el * 68 + kp]     = bfpack(v0, v1);
        smw[SW_AHI + el * 68 + kp + 1] = bfpack(v2, v3);
        float h0 = __bfloat162float(__float2bfloat16(v0));
        float h1 = __bfloat162float(__float2bfloat16(v1));
        float h2v = __bfloat162float(__float2bfloat16(v2));
        float h3 = __bfloat162float(__float2bfloat16(v3));
        smw[SW_ALO + el * 68 + kp]     = bfpack(v0 - h0, v1 - h1);
        smw[SW_ALO + el * 68 + kp + 1] = bfpack(v2 - h2v, v3 - h3);
    }
    __syncthreads();

    // ---- layer-2 GEMM: 8 warps, warp (mw,nw) owns 32 rows x 32 cols ----
    const int mw = wid & 1, nw = wid >> 1;       // nw in 0..3
    const int m0 = mw * 32;
    float acc[2][4][4];
#pragma unroll
    for (int mt = 0; mt < 2; ++mt)
#pragma unroll
        for (int nt = 0; nt < 4; ++nt)
#pragma unroll
            for (int c = 0; c < 4; ++c) acc[mt][nt][c] = 0.0f;

    const uint32_t aoff = ((m0 + (lane & 7) + ((lane >> 3) & 1) * 8) * 68 + (lane >> 4) * 4) * 4;

#pragma unroll 1
    for (int sp = 0; sp < 3; ++sp) {
        const uint32_t Ab = smb + (sp == 1 ? SW_ALO : SW_AHI) * 4 + aoff;
        const ull* Bp = g_Bfrag + (sp == 2 ? 4096 : 0) + nw * 4 * 32 + lane;
#pragma unroll
        for (int kk = 0; kk < 8; ++kk) {
            uint32_t af[2][4];
            ldsm4(af[0], Ab + kk * 32);
            ldsm4(af[1], Ab + 16 * 68 * 4 + kk * 32);
            const ull* Bk = Bp + kk * 512;
            ull bfr[4];
#pragma unroll
            for (int nt = 0; nt < 4; ++nt) bfr[nt] = Bk[nt * 32];   // LDG.64, L1-hot
#pragma unroll
            for (int mt = 0; mt < 2; ++mt)
#pragma unroll
                for (int nt = 0; nt < 4; ++nt)
                    mma16816(acc[mt][nt], af[mt],
                             (uint32_t)bfr[nt], (uint32_t)(bfr[nt] >> 32));
        }
    }
    __syncthreads();   // all A reads complete before h2 overwrites the region

    // ---- convert: h2 = relu(D + b2) -> split-bf16 into A region (frag layout) ----
    {
        const int r = lane >> 2, c2 = lane & 3;
#pragma unroll
        for (int mt = 0; mt < 2; ++mt)
#pragma unroll
            for (int nt = 0; nt < 4; ++nt) {
                int j = nw * 32 + nt * 8 + 2 * c2;
                float bj0 = smf[SW_B2 + j], bj1 = smf[SW_B2 + j + 1];
                int row0 = m0 + mt * 16 + r;
                float v0 = fmaxf(acc[mt][nt][0] + bj0, 0.f);
                float v1 = fmaxf(acc[mt][nt][1] + bj1, 0.f);
                float v2 = fmaxf(acc[mt][nt][2] + bj0, 0.f);
                float v3 = fmaxf(acc[mt][nt][3] + bj1, 0.f);
                int w0i = row0 * 68 + (j >> 1);
                int w1i = (row0 + 8) * 68 + (j >> 1);
                smw[SW_AHI + w0i] = bfpack(v0, v1);
                smw[SW_AHI + w1i] = bfpack(v2, v3);
                float p0 = __bfloat162float(__float2bfloat16(v0));
                float p1 = __bfloat162float(__float2bfloat16(v1));
                float p2 = __bfloat162float(__float2bfloat16(v2));
                float p3 = __bfloat162float(__float2bfloat16(v3));
                smw[SW_ALO + w0i] = bfpack(v0 - p0, v1 - p1);
                smw[SW_ALO + w1i] = bfpack(v2 - p2, v3 - p3);
            }
    }
    __syncthreads();

    // ---- layer-3 MMA on warps 0..3: M=64 (16 rows/warp), N=16, K=128 ----
    if (wid < 4) {
        float acc2[2][4];
#pragma unroll
        for (int nt = 0; nt < 2; ++nt)
#pragma unroll
            for (int c = 0; c < 4; ++c) acc2[nt][c] = 0.0f;

        const uint32_t a2off = ((wid * 16 + (lane & 7) + ((lane >> 3) & 1) * 8) * 68 + (lane >> 4) * 4) * 4;
#pragma unroll 1
        for (int sp = 0; sp < 3; ++sp) {
            const uint32_t Ab = smb + (sp == 1 ? SW_ALO : SW_AHI) * 4 + a2off;
            const ull* Wp = g_W3frag + (sp == 2 ? 512 : 0) + lane;
#pragma unroll
            for (int kk = 0; kk < 8; ++kk) {
                uint32_t af[4];
                ldsm4(af, Ab + kk * 32);
                ull f0 = Wp[kk * 64];
                ull f1 = Wp[kk * 64 + 32];
                mma16816(acc2[0], af, (uint32_t)f0, (uint32_t)(f0 >> 32));
                mma16816(acc2[1], af, (uint32_t)f1, (uint32_t)(f1 >> 32));
            }
        }
        // resp to smem: rows = electrons, cols = sensors
        const int r = lane >> 2, c2 = lane & 3;
#pragma unroll
        for (int nt = 0; nt < 2; ++nt) {
            int j = nt * 8 + 2 * c2;
            if (j < SS) {
                int row0 = wid * 16 + r;
                *(float2*)&smf[SW_RESP + row0 * SS + j] = make_float2(acc2[nt][0], acc2[nt][1]);
                *(float2*)&smf[SW_RESP + (row0 + 8) * SS + j] = make_float2(acc2[nt][2], acc2[nt][3]);
            }
        }
    }
    __syncthreads();

    // ---- sparse Gaussian scatter (exp(-5d^2) < 3e-20 beyond |d|=3) ----
    {
        float resp[SS];
#pragma unroll
        for (int s = 0; s < SS; ++s)
            resp[s] = smf[SW_RESP + el * SS + s] + smf[SW_B3 + s];

        const float z = x2;
        const float c = msk * MASK_COEF;
        int t0 = (int)ceilf(z - 3.0f);
        int t1 = (int)floorf(z + 3.0f);
        if (t0 < 0) t0 = 0;
        if (t1 > TT - 1) t1 = TT - 1;
        const int b = eg / 10000;
        float* ob = out + (size_t)b * SS * TT;
        for (int t = t0 + q; t <= t1; t += 4) {     // ticks split across 4 threads
            float d = (float)t - z;
            float w = __expf(-5.0f * d * d) * c;
#pragma unroll
            for (int s = 0; s < SS; ++s)
                atomicAdd(&ob[s * TT + t], w * resp[s]);
        }
    }
}

extern "C" void kernel_launch(void* const* d_in, const int* in_sizes, int n_in,
                              void* d_out, int out_size) {
    const float* de   = (const float*)d_in[0];
    const float* mask = (const float*)d_in[1];
    const float* W1   = (const float*)d_in[2];
    const float* b1   = (const float*)d_in[3];
    const float* W2   = (const float*)d_in[4];
    const float* b2   = (const float*)d_in[5];
    const float* W3   = (const float*)d_in[6];
    const float* b3   = (const float*)d_in[7];
    float* out = (float*)d_out;

    prep_zero_kernel<<<188, 256>>>(W2, W3, (float4*)out);

    const int smem_bytes = SW_TOT * 4;  // 38464
    cudaFuncSetAttribute(fused_sensor_kernel,
                         cudaFuncAttributeMaxDynamicSharedMemorySize, smem_bytes);

    fused_sensor_kernel<<<NE / EB, 256, smem_bytes>>>(   // 1250 CTAs
        de, mask, W1, b1, b2, b3, out);
}

// round 14
// speedup vs baseline: 1.2013x; 1.2013x over previous
#include <cuda_runtime.h>
#include <cuda_bf16.h>
#include <math.h>
#include <stdint.h>

typedef unsigned long long ull;

#define NE 80000
#define TT 2000
#define SS 12
#define HH 128
#define EB 64                      // electrons per CTA (MMA M)
#define MASK_COEF 1.2615662610f    // GAUSS_NORM / sqrt(0.1)

// smem word offsets
#define SW_AHI 0                   // 64 x 68 (bf16x2 k-pairs, padded stride); reused for h2-hi
#define SW_ALO (SW_AHI + EB*68)    // 4352; reused for h2-lo
#define SW_B2  (SW_ALO + EB*68)    // 8704
#define SW_B3  (SW_B2 + HH)        // 8832 (+16)
#define SW_RESP (SW_B3 + 16)       // 8848: 64 x 12 f32
#define SW_TOT (SW_RESP + EB*SS)   // 9616 words = 38464 B

// W2 fragments: [spB(2)][kk(8)][ntile(16)][lane(32)] -> (b0,b1)
__device__ ull g_Bfrag[2 * 8 * 16 * 32];
// W3 fragments: [spB(2)][kk(8)][ntile(2)][lane(32)]  (N=16: sensors 0..11 + pad)
__device__ ull g_W3frag[2 * 8 * 2 * 32];

__device__ __forceinline__ uint32_t bfpack(float a, float b) {
    __nv_bfloat162 t(__float2bfloat16(a), __float2bfloat16(b));
    return *(uint32_t*)&t;
}
__device__ __forceinline__ uint32_t smem_u32(const void* p) {
    uint32_t a;
    asm("{ .reg .u64 t; cvta.to.shared.u64 t, %1; cvt.u32.u64 %0, t; }" : "=r"(a) : "l"(p));
    return a;
}
__device__ __forceinline__ void ldsm4(uint32_t* r, uint32_t addr) {
    asm volatile("ldmatrix.sync.aligned.m8n8.x4.shared.b16 {%0,%1,%2,%3}, [%4];"
        : "=r"(r[0]), "=r"(r[1]), "=r"(r[2]), "=r"(r[3]) : "r"(addr));
}
__device__ __forceinline__ void mma16816(float* c, const uint32_t* a, uint32_t b0, uint32_t b1) {
    asm volatile(
        "mma.sync.aligned.m16n8k16.row.col.f32.bf16.bf16.f32 "
        "{%0,%1,%2,%3}, {%4,%5,%6,%7}, {%8,%9}, {%0,%1,%2,%3};"
        : "+f"(c[0]), "+f"(c[1]), "+f"(c[2]), "+f"(c[3])
        : "r"(a[0]), "r"(a[1]), "r"(a[2]), "r"(a[3]), "r"(b0), "r"(b1));
}
__device__ __forceinline__ void red4(float* p, float a, float b, float c, float d) {
    asm volatile("red.global.add.v4.f32 [%0], {%1,%2,%3,%4};"
        :: "l"(p), "f"(a), "f"(b), "f"(c), "f"(d) : "memory");
}

// one launch: zero output + pack W2 fragments + pack W3 fragments (R11-validated)
__global__ void prep_zero_kernel(const float* __restrict__ W2,
                                 const float* __restrict__ W3,
                                 float4* __restrict__ out4) {
    int idx = blockIdx.x * 256 + threadIdx.x;
    if (idx < 48000) out4[idx] = make_float4(0.f, 0.f, 0.f, 0.f);

    if (idx < 8192) {
        int lane  = idx & 31;
        int ntile = (idx >> 5) & 15;
        int kk    = (idx >> 9) & 7;
        int spB   = idx >> 12;
        int kp0 = kk * 8 + (lane & 3);
        int n   = ntile * 8 + (lane >> 2);
        float v0 = W2[(2 * kp0) * HH + n];
        float v1 = W2[(2 * kp0 + 1) * HH + n];
        float w0 = W2[(2 * (kp0 + 4)) * HH + n];
        float w1 = W2[(2 * (kp0 + 4) + 1) * HH + n];
        uint32_t b0, b1;
        if (spB == 0) { b0 = bfpack(v0, v1); b1 = bfpack(w0, w1); }
        else {
            b0 = bfpack(v0 - __bfloat162float(__float2bfloat16(v0)),
                        v1 - __bfloat162float(__float2bfloat16(v1)));
            b1 = bfpack(w0 - __bfloat162float(__float2bfloat16(w0)),
                        w1 - __bfloat162float(__float2bfloat16(w1)));
        }
        g_Bfrag[idx] = ((ull)b1 << 32) | (ull)b0;
    } else if (idx < 8192 + 1024) {
        int t = idx - 8192;
        int lane = t & 31;
        int nt   = (t >> 5) & 1;
        int kk   = (t >> 6) & 7;
        int spB  = t >> 9;
        int kp0 = kk * 8 + (lane & 3);
        int n   = nt * 8 + (lane >> 2);
        float v0 = 0.f, v1 = 0.f, w0 = 0.f, w1 = 0.f;
        if (n < SS) {
            v0 = W3[(2 * kp0) * SS + n];
            v1 = W3[(2 * kp0 + 1) * SS + n];
            w0 = W3[(2 * (kp0 + 4)) * SS + n];
            w1 = W3[(2 * (kp0 + 4) + 1) * SS + n];
        }
        uint32_t b0, b1;
        if (spB == 0) { b0 = bfpack(v0, v1); b1 = bfpack(w0, w1); }
        else {
            b0 = bfpack(v0 - __bfloat162float(__float2bfloat16(v0)),
                        v1 - __bfloat162float(__float2bfloat16(v1)));
            b1 = bfpack(w0 - __bfloat162float(__float2bfloat16(w0)),
                        w1 - __bfloat162float(__float2bfloat16(w1)));
        }
        g_W3frag[t] = ((ull)b1 << 32) | (ull)b0;
    }
}

__global__ __launch_bounds__(128, 4)
void fused_sensor_kernel(
    const float* __restrict__ de,    // (B,N,3)
    const float* __restrict__ mask,  // (B,N)
    const float* __restrict__ W1,    // (3,H)
    const float* __restrict__ b1,    // (H)
    const float* __restrict__ b2,    // (H)
    const float* __restrict__ b3,    // (S)
    float* __restrict__ out)         // (B,S,T)
{
    extern __shared__ uint32_t smw[];
    float* smf = (float*)smw;
    const uint32_t smb = smem_u32(smw);
    const int tid  = threadIdx.x;
    const int lane = tid & 31;
    const int wid  = tid >> 5;

    // ---- small biases to smem ----
    if (tid < HH) smf[SW_B2 + tid] = b2[tid];
    if (tid < SS) smf[SW_B3 + tid] = b3[tid];

    // ---- layer 1 -> A hi/lo (2 threads/electron, vectorized W1 loads) ----
    const int el = tid >> 1;
    const int q  = tid & 1;
    const int eg = blockIdx.x * EB + el;
    const float x0 = de[3 * eg + 0];
    const float x1 = de[3 * eg + 1];
    const float x2 = de[3 * eg + 2];
    const float msk = mask[eg];
#pragma unroll 4
    for (int i4 = 0; i4 < 16; ++i4) {
        int k = q * 64 + i4 * 4;
        float4 wa = *(const float4*)&W1[k];
        float4 wb = *(const float4*)&W1[HH + k];
        float4 wc = *(const float4*)&W1[2 * HH + k];
        float4 bb = *(const float4*)&b1[k];
        float v0 = fmaxf(fmaf(x2, wc.x, fmaf(x1, wb.x, fmaf(x0, wa.x, bb.x))), 0.f);
        float v1 = fmaxf(fmaf(x2, wc.y, fmaf(x1, wb.y, fmaf(x0, wa.y, bb.y))), 0.f);
        float v2 = fmaxf(fmaf(x2, wc.z, fmaf(x1, wb.z, fmaf(x0, wa.z, bb.z))), 0.f);
        float v3 = fmaxf(fmaf(x2, wc.w, fmaf(x1, wb.w, fmaf(x0, wa.w, bb.w))), 0.f);
        int kp = k >> 1;
        smw[SW_AHI + el * 68 + kp]     = bfpack(v0, v1);
        smw[SW_AHI + el * 68 + kp + 1] = bfpack(v2, v3);
        float h0 = __bfloat162float(__float2bfloat16(v0));
        float h1 = __bfloat162float(__float2bfloat16(v1));
        float h2v = __bfloat162float(__float2bfloat16(v2));
        float h3 = __bfloat162float(__float2bfloat16(v3));
        smw[SW_ALO + el * 68 + kp]     = bfpack(v0 - h0, v1 - h1);
        smw[SW_ALO + el * 68 + kp + 1] = bfpack(v2 - h2v, v3 - h3);
    }
    __syncthreads();

    // ---- layer-2 GEMM: warp (mw,nw) owns 32 rows x 64 cols (R9/R11-validated) ----
    const int mw = wid & 1, nw = wid >> 1;
    const int m0 = mw * 32;
    float acc[2][8][4];
#pragma unroll
    for (int mt = 0; mt < 2; ++mt)
#pragma unroll
        for (int nt = 0; nt < 8; ++nt)
#pragma unroll
            for (int c = 0; c < 4; ++c) acc[mt][nt][c] = 0.0f;

    const uint32_t aoff = ((m0 + (lane & 7) + ((lane >> 3) & 1) * 8) * 68 + (lane >> 4) * 4) * 4;

#pragma unroll 1
    for (int sp = 0; sp < 3; ++sp) {
        const uint32_t Ab = smb + (sp == 1 ? SW_ALO : SW_AHI) * 4 + aoff;
        const ull* Bp = g_Bfrag + (sp == 2 ? 4096 : 0) + nw * 8 * 32 + lane;
#pragma unroll
        for (int kk = 0; kk < 8; ++kk) {
            uint32_t af[2][4];
            ldsm4(af[0], Ab + kk * 32);
            ldsm4(af[1], Ab + 16 * 68 * 4 + kk * 32);
            const ull* Bk = Bp + kk * 512;
            ull bfr[8];
#pragma unroll
            for (int nt = 0; nt < 8; ++nt) bfr[nt] = Bk[nt * 32];
#pragma unroll
            for (int mt = 0; mt < 2; ++mt)
#pragma unroll
                for (int nt = 0; nt < 8; ++nt)
                    mma16816(acc[mt][nt], af[mt],
                             (uint32_t)bfr[nt], (uint32_t)(bfr[nt] >> 32));
        }
    }
    __syncthreads();   // all A reads complete before h2 overwrites the region

    // ---- convert: h2 = relu(D + b2) -> split-bf16 into A region (frag layout) ----
    {
        const int r = lane >> 2, c2 = lane & 3;
#pragma unroll
        for (int mt = 0; mt < 2; ++mt)
#pragma unroll
            for (int nt = 0; nt < 8; ++nt) {
                int j = nw * 64 + nt * 8 + 2 * c2;
                float bj0 = smf[SW_B2 + j], bj1 = smf[SW_B2 + j + 1];
                int row0 = m0 + mt * 16 + r;
                float v0 = fmaxf(acc[mt][nt][0] + bj0, 0.f);
                float v1 = fmaxf(acc[mt][nt][1] + bj1, 0.f);
                float v2 = fmaxf(acc[mt][nt][2] + bj0, 0.f);
                float v3 = fmaxf(acc[mt][nt][3] + bj1, 0.f);
                int w0i = row0 * 68 + (j >> 1);
                int w1i = (row0 + 8) * 68 + (j >> 1);
                smw[SW_AHI + w0i] = bfpack(v0, v1);
                smw[SW_AHI + w1i] = bfpack(v2, v3);
                float p0 = __bfloat162float(__float2bfloat16(v0));
                float p1 = __bfloat162float(__float2bfloat16(v1));
                float p2 = __bfloat162float(__float2bfloat16(v2));
                float p3 = __bfloat162float(__float2bfloat16(v3));
                smw[SW_ALO + w0i] = bfpack(v0 - p0, v1 - p1);
                smw[SW_ALO + w1i] = bfpack(v2 - p2, v3 - p3);
            }
    }
    __syncthreads();

    // ---- layer-3 MMA: M=64 (16 rows/warp), N=16, K=128 ----
    {
        float acc2[2][4];
#pragma unroll
        for (int nt = 0; nt < 2; ++nt)
#pragma unroll
            for (int c = 0; c < 4; ++c) acc2[nt][c] = 0.0f;

        const uint32_t a2off = ((wid * 16 + (lane & 7) + ((lane >> 3) & 1) * 8) * 68 + (lane >> 4) * 4) * 4;
#pragma unroll 1
        for (int sp = 0; sp < 3; ++sp) {
            const uint32_t Ab = smb + (sp == 1 ? SW_ALO : SW_AHI) * 4 + a2off;
            const ull* Wp = g_W3frag + (sp == 2 ? 512 : 0) + lane;
#pragma unroll
            for (int kk = 0; kk < 8; ++kk) {
                uint32_t af[4];
                ldsm4(af, Ab + kk * 32);
                ull f0 = Wp[kk * 64];
                ull f1 = Wp[kk * 64 + 32];
                mma16816(acc2[0], af, (uint32_t)f0, (uint32_t)(f0 >> 32));
                mma16816(acc2[1], af, (uint32_t)f1, (uint32_t)(f1 >> 32));
            }
        }
        // resp to smem: rows = electrons, cols = sensors
        const int r = lane >> 2, c2 = lane & 3;
#pragma unroll
        for (int nt = 0; nt < 2; ++nt) {
            int j = nt * 8 + 2 * c2;
            if (j < SS) {
                int row0 = wid * 16 + r;
                *(float2*)&smf[SW_RESP + row0 * SS + j] = make_float2(acc2[nt][0], acc2[nt][1]);
                *(float2*)&smf[SW_RESP + (row0 + 8) * SS + j] = make_float2(acc2[nt][2], acc2[nt][3]);
            }
        }
    }
    __syncthreads();

    // ---- Gaussian scatter: 12-tick aligned window, red.v4 (sm_90+) ----
    {
        float resp[SS];
#pragma unroll
        for (int s = 0; s < SS; ++s)
            resp[s] = smf[SW_RESP + el * SS + s] + smf[SW_B3 + s];

        const float z = x2;
        const float c = msk * MASK_COEF;
        // aligned window [ta, ta+12) covering |t-z|<=3 support (proof in theory)
        int ta = ((int)z - 4) & ~3;
        if (ta < 0) ta = 0;
        if (ta > TT - 12) ta = TT - 12;
        float w[12];
#pragma unroll
        for (int i = 0; i < 12; ++i) {
            float d = (float)(ta + i) - z;
            w[i] = __expf(-5.0f * d * d) * c;
        }
        const int b = eg / 10000;
        float* ob = out + (size_t)b * SS * TT + ta;
#pragma unroll 2
        for (int s = q; s < SS; s += 2) {       // 6 sensors per thread
            float r0 = resp[s];
            float* p = ob + s * TT;
            red4(p,     w[0] * r0, w[1] * r0, w[2] * r0,  w[3] * r0);
            red4(p + 4, w[4] * r0, w[5] * r0, w[6] * r0,  w[7] * r0);
            red4(p + 8, w[8] * r0, w[9] * r0, w[10] * r0, w[11] * r0);
        }
    }
}

extern "C" void kernel_launch(void* const* d_in, const int* in_sizes, int n_in,
                              void* d_out, int out_size) {
    const float* de   = (const float*)d_in[0];
    const float* mask = (const float*)d_in[1];
    const float* W1   = (const float*)d_in[2];
    const float* b1   = (const float*)d_in[3];
    const float* W2   = (const float*)d_in[4];
    const float* b2   = (const float*)d_in[5];
    const float* W3   = (const float*)d_in[6];
    const float* b3   = (const float*)d_in[7];
    float* out = (float*)d_out;

    prep_zero_kernel<<<188, 256>>>(W2, W3, (float4*)out);

    const int smem_bytes = SW_TOT * 4;  // 38464
    cudaFuncSetAttribute(fused_sensor_kernel,
                         cudaFuncAttributeMaxDynamicSharedMemorySize, smem_bytes);

    fused_sensor_kernel<<<NE / EB, 128, smem_bytes>>>(   // 1250 CTAs
        de, mask, W1, b1, b2, b3, out);
}

// round 15
// speedup vs baseline: 1.2516x; 1.0418x over previous
#include <cuda_runtime.h>
#include <cuda_bf16.h>
#include <math.h>
#include <stdint.h>

typedef unsigned long long ull;

#define NE 80000
#define TT 2000
#define SS 12
#define HH 128
#define EB 64                      // electrons per CTA (MMA M)
#define MASK_COEF 1.2615662610f    // GAUSS_NORM / sqrt(0.1)

// smem word offsets
#define SW_AHI 0                   // 64 x 68 (bf16x2 k-pairs, padded stride); reused for h2-hi
#define SW_ALO (SW_AHI + EB*68)    // 4352; reused for h2-lo
#define SW_B2  (SW_ALO + EB*68)    // 8704
#define SW_B3  (SW_B2 + HH)        // 8832 (+16)
#define SW_RESP (SW_B3 + 16)       // 8848: 64 x 12 f32
#define SW_W1  (SW_RESP + EB*SS)   // 9616: W1 rows (3x128) + b1 (128)
#define SW_TOT (SW_W1 + 512)       // 10128 words = 40512 B

// W2 fragments packed in pairs: [spB(2)][kk(8)][npair(8)][lane(32)] -> (nt even, nt odd)
__device__ ulonglong2 g_Bfrag2[2 * 8 * 8 * 32];
// W3 fragments packed: [spB(2)][kk(8)][lane(32)] -> (nt0, nt1)
__device__ ulonglong2 g_W3frag2[2 * 8 * 32];

__device__ __forceinline__ uint32_t bfpack(float a, float b) {
    __nv_bfloat162 t(__float2bfloat16(a), __float2bfloat16(b));
    return *(uint32_t*)&t;
}
__device__ __forceinline__ uint32_t smem_u32(const void* p) {
    uint32_t a;
    asm("{ .reg .u64 t; cvta.to.shared.u64 t, %1; cvt.u32.u64 %0, t; }" : "=r"(a) : "l"(p));
    return a;
}
__device__ __forceinline__ void ldsm4(uint32_t* r, uint32_t addr) {
    asm volatile("ldmatrix.sync.aligned.m8n8.x4.shared.b16 {%0,%1,%2,%3}, [%4];"
        : "=r"(r[0]), "=r"(r[1]), "=r"(r[2]), "=r"(r[3]) : "r"(addr));
}
__device__ __forceinline__ void mma16816(float* c, const uint32_t* a, uint32_t b0, uint32_t b1) {
    asm volatile(
        "mma.sync.aligned.m16n8k16.row.col.f32.bf16.bf16.f32 "
        "{%0,%1,%2,%3}, {%4,%5,%6,%7}, {%8,%9}, {%0,%1,%2,%3};"
        : "+f"(c[0]), "+f"(c[1]), "+f"(c[2]), "+f"(c[3])
        : "r"(a[0]), "r"(a[1]), "r"(a[2]), "r"(a[3]), "r"(b0), "r"(b1));
}
__device__ __forceinline__ void mma_u(float* c, const uint32_t* a, ull b) {
    mma16816(c, a, (uint32_t)b, (uint32_t)(b >> 32));
}

// one launch: zero output + pack W2/W3 fragments (indexing identical to the
// validated R11 prep; only the *storage address* changed to paired layout)
__global__ void prep_zero_kernel(const float* __restrict__ W2,
                                 const float* __restrict__ W3,
                                 float4* __restrict__ out4) {
    int idx = blockIdx.x * 256 + threadIdx.x;
    if (idx < 48000) out4[idx] = make_float4(0.f, 0.f, 0.f, 0.f);

    if (idx < 8192) {
        int lane  = idx & 31;
        int ntile = (idx >> 5) & 15;
        int kk    = (idx >> 9) & 7;
        int spB   = idx >> 12;
        int kp0 = kk * 8 + (lane & 3);
        int n   = ntile * 8 + (lane >> 2);
        float v0 = W2[(2 * kp0) * HH + n];
        float v1 = W2[(2 * kp0 + 1) * HH + n];
        float w0 = W2[(2 * (kp0 + 4)) * HH + n];
        float w1 = W2[(2 * (kp0 + 4) + 1) * HH + n];
        uint32_t b0, b1;
        if (spB == 0) { b0 = bfpack(v0, v1); b1 = bfpack(w0, w1); }
        else {
            b0 = bfpack(v0 - __bfloat162float(__float2bfloat16(v0)),
                        v1 - __bfloat162float(__float2bfloat16(v1)));
            b1 = bfpack(w0 - __bfloat162float(__float2bfloat16(w0)),
                        w1 - __bfloat162float(__float2bfloat16(w1)));
        }
        ull v = ((ull)b1 << 32) | (ull)b0;
        int base = ((spB * 8 + kk) * 8 + (ntile >> 1)) * 32 + lane;
        if (ntile & 1) g_Bfrag2[base].y = v; else g_Bfrag2[base].x = v;
    } else if (idx < 8192 + 1024) {
        int t = idx - 8192;
        int lane = t & 31;
        int nt   = (t >> 5) & 1;
        int kk   = (t >> 6) & 7;
        int spB  = t >> 9;
        int kp0 = kk * 8 + (lane & 3);
        int n   = nt * 8 + (lane >> 2);
        float v0 = 0.f, v1 = 0.f, w0 = 0.f, w1 = 0.f;
        if (n < SS) {
            v0 = W3[(2 * kp0) * SS + n];
            v1 = W3[(2 * kp0 + 1) * SS + n];
            w0 = W3[(2 * (kp0 + 4)) * SS + n];
            w1 = W3[(2 * (kp0 + 4) + 1) * SS + n];
        }
        uint32_t b0, b1;
        if (spB == 0) { b0 = bfpack(v0, v1); b1 = bfpack(w0, w1); }
        else {
            b0 = bfpack(v0 - __bfloat162float(__float2bfloat16(v0)),
                        v1 - __bfloat162float(__float2bfloat16(v1)));
            b1 = bfpack(w0 - __bfloat162float(__float2bfloat16(w0)),
                        w1 - __bfloat162float(__float2bfloat16(w1)));
        }
        ull v = ((ull)b1 << 32) | (ull)b0;
        int base = (spB * 8 + kk) * 32 + lane;
        if (nt) g_W3frag2[base].y = v; else g_W3frag2[base].x = v;
    }
}

__global__ __launch_bounds__(128, 4)
void fused_sensor_kernel(
    const float* __restrict__ de,    // (B,N,3)
    const float* __restrict__ mask,  // (B,N)
    const float* __restrict__ W1,    // (3,H)
    const float* __restrict__ b1,    // (H)
    const float* __restrict__ b2,    // (H)
    const float* __restrict__ b3,    // (S)
    float* __restrict__ out)         // (B,S,T)
{
    extern __shared__ uint32_t smw[];
    float* smf = (float*)smw;
    const uint32_t smb = smem_u32(smw);
    const int tid  = threadIdx.x;
    const int lane = tid & 31;
    const int wid  = tid >> 5;

    // ---- stage small weights to smem (W1+b1+b2+b3) ----
    for (int i = tid; i < 3 * HH; i += 128) smf[SW_W1 + i] = W1[i];
    if (tid < HH) {
        smf[SW_W1 + 384 + tid] = b1[tid];
        smf[SW_B2 + tid] = b2[tid];
    }
    if (tid < SS) smf[SW_B3 + tid] = b3[tid];

    // electron inputs (2 threads/electron)
    const int el = tid >> 1;
    const int q  = tid & 1;
    const int eg = blockIdx.x * EB + el;
    const float x0 = de[3 * eg + 0];
    const float x1 = de[3 * eg + 1];
    const float x2 = de[3 * eg + 2];
    const float msk = mask[eg];
    __syncthreads();

    // ---- layer 1 -> A hi/lo via smem-broadcast LDS.128 ----
#pragma unroll 4
    for (int i4 = 0; i4 < 16; ++i4) {
        int k = q * 64 + i4 * 4;
        float4 wa = *(const float4*)&smf[SW_W1 + k];
        float4 wb = *(const float4*)&smf[SW_W1 + 128 + k];
        float4 wc = *(const float4*)&smf[SW_W1 + 256 + k];
        float4 bb = *(const float4*)&smf[SW_W1 + 384 + k];
        float v0 = fmaxf(fmaf(x2, wc.x, fmaf(x1, wb.x, fmaf(x0, wa.x, bb.x))), 0.f);
        float v1 = fmaxf(fmaf(x2, wc.y, fmaf(x1, wb.y, fmaf(x0, wa.y, bb.y))), 0.f);
        float v2 = fmaxf(fmaf(x2, wc.z, fmaf(x1, wb.z, fmaf(x0, wa.z, bb.z))), 0.f);
        float v3 = fmaxf(fmaf(x2, wc.w, fmaf(x1, wb.w, fmaf(x0, wa.w, bb.w))), 0.f);
        int kp = k >> 1;
        smw[SW_AHI + el * 68 + kp]     = bfpack(v0, v1);
        smw[SW_AHI + el * 68 + kp + 1] = bfpack(v2, v3);
        float h0 = __bfloat162float(__float2bfloat16(v0));
        float h1 = __bfloat162float(__float2bfloat16(v1));
        float h2v = __bfloat162float(__float2bfloat16(v2));
        float h3 = __bfloat162float(__float2bfloat16(v3));
        smw[SW_ALO + el * 68 + kp]     = bfpack(v0 - h0, v1 - h1);
        smw[SW_ALO + el * 68 + kp + 1] = bfpack(v2 - h2v, v3 - h3);
    }
    __syncthreads();

    // ---- layer-2 GEMM: warp (mw,nw) owns 32 rows x 64 cols ----
    const int mw = wid & 1, nw = wid >> 1;
    const int m0 = mw * 32;
    float acc[2][8][4];
#pragma unroll
    for (int mt = 0; mt < 2; ++mt)
#pragma unroll
        for (int nt = 0; nt < 8; ++nt)
#pragma unroll
            for (int c = 0; c < 4; ++c) acc[mt][nt][c] = 0.0f;

    const uint32_t aoff = ((m0 + (lane & 7) + ((lane >> 3) & 1) * 8) * 68 + (lane >> 4) * 4) * 4;

#pragma unroll 1
    for (int sp = 0; sp < 3; ++sp) {
        const uint32_t Ab = smb + (sp == 1 ? SW_ALO : SW_AHI) * 4 + aoff;
        const ulonglong2* Bp = g_Bfrag2 + (sp == 2 ? 2048 : 0) + nw * 4 * 32 + lane;
#pragma unroll
        for (int kk = 0; kk < 8; ++kk) {
            uint32_t af[2][4];
            ldsm4(af[0], Ab + kk * 32);
            ldsm4(af[1], Ab + 16 * 68 * 4 + kk * 32);
            const ulonglong2* Bk = Bp + kk * 256;
            ulonglong2 u0 = Bk[0], u1 = Bk[32], u2 = Bk[64], u3 = Bk[96];  // LDG.128 x4
#pragma unroll
            for (int mt = 0; mt < 2; ++mt) {
                mma_u(acc[mt][0], af[mt], u0.x);
                mma_u(acc[mt][1], af[mt], u0.y);
                mma_u(acc[mt][2], af[mt], u1.x);
                mma_u(acc[mt][3], af[mt], u1.y);
                mma_u(acc[mt][4], af[mt], u2.x);
                mma_u(acc[mt][5], af[mt], u2.y);
                mma_u(acc[mt][6], af[mt], u3.x);
                mma_u(acc[mt][7], af[mt], u3.y);
            }
        }
    }
    __syncthreads();   // all A reads complete before h2 overwrites the region

    // ---- convert: h2 = relu(D + b2) -> split-bf16 into A region (frag layout) ----
    {
        const int r = lane >> 2, c2 = lane & 3;
#pragma unroll
        for (int mt = 0; mt < 2; ++mt)
#pragma unroll
            for (int nt = 0; nt < 8; ++nt) {
                int j = nw * 64 + nt * 8 + 2 * c2;
                float bj0 = smf[SW_B2 + j], bj1 = smf[SW_B2 + j + 1];
                int row0 = m0 + mt * 16 + r;
                float v0 = fmaxf(acc[mt][nt][0] + bj0, 0.f);
                float v1 = fmaxf(acc[mt][nt][1] + bj1, 0.f);
                float v2 = fmaxf(acc[mt][nt][2] + bj0, 0.f);
                float v3 = fmaxf(acc[mt][nt][3] + bj1, 0.f);
                int w0i = row0 * 68 + (j >> 1);
                int w1i = (row0 + 8) * 68 + (j >> 1);
                smw[SW_AHI + w0i] = bfpack(v0, v1);
                smw[SW_AHI + w1i] = bfpack(v2, v3);
                float p0 = __bfloat162float(__float2bfloat16(v0));
                float p1 = __bfloat162float(__float2bfloat16(v1));
                float p2 = __bfloat162float(__float2bfloat16(v2));
                float p3 = __bfloat162float(__float2bfloat16(v3));
                smw[SW_ALO + w0i] = bfpack(v0 - p0, v1 - p1);
                smw[SW_ALO + w1i] = bfpack(v2 - p2, v3 - p3);
            }
    }
    __syncthreads();

    // ---- layer-3 MMA: M=64 (16 rows/warp), N=16, K=128 ----
    {
        float acc2[2][4];
#pragma unroll
        for (int nt = 0; nt < 2; ++nt)
#pragma unroll
            for (int c = 0; c < 4; ++c) acc2[nt][c] = 0.0f;

        const uint32_t a2off = ((wid * 16 + (lane & 7) + ((lane >> 3) & 1) * 8) * 68 + (lane >> 4) * 4) * 4;
#pragma unroll 1
        for (int sp = 0; sp < 3; ++sp) {
            const uint32_t Ab = smb + (sp == 1 ? SW_ALO : SW_AHI) * 4 + a2off;
            const ulonglong2* Wp = g_W3frag2 + (sp == 2 ? 256 : 0) + lane;
#pragma unroll
            for (int kk = 0; kk < 8; ++kk) {
                uint32_t af[4];
                ldsm4(af, Ab + kk * 32);
                ulonglong2 f = Wp[kk * 32];          // LDG.128
                mma_u(acc2[0], af, f.x);
                mma_u(acc2[1], af, f.y);
            }
        }
        // resp to smem: rows = electrons, cols = sensors
        const int r = lane >> 2, c2 = lane & 3;
#pragma unroll
        for (int nt = 0; nt < 2; ++nt) {
            int j = nt * 8 + 2 * c2;
            if (j < SS) {
                int row0 = wid * 16 + r;
                *(float2*)&smf[SW_RESP + row0 * SS + j] = make_float2(acc2[nt][0], acc2[nt][1]);
                *(float2*)&smf[SW_RESP + (row0 + 8) * SS + j] = make_float2(acc2[nt][2], acc2[nt][3]);
            }
        }
    }
    __syncthreads();

    // ---- sparse Gaussian scatter (R12 scalar form; exp(-5d^2)<3e-20 beyond |d|=3) ----
    {
        float resp[SS];
#pragma unroll
        for (int s = 0; s < SS; ++s)
            resp[s] = smf[SW_RESP + el * SS + s] + smf[SW_B3 + s];

        const float z = x2;
        const float c = msk * MASK_COEF;
        int t0 = (int)ceilf(z - 3.0f);
        int t1 = (int)floorf(z + 3.0f);
        if (t0 < 0) t0 = 0;
        if (t1 > TT - 1) t1 = TT - 1;
        const int b = eg / 10000;
        float* ob = out + (size_t)b * SS * TT;
        for (int t = t0 + q; t <= t1; t += 2) {
            float d = (float)t - z;
            float w = __expf(-5.0f * d * d) * c;
#pragma unroll
            for (int s = 0; s < SS; ++s)
                atomicAdd(&ob[s * TT + t], w * resp[s]);
        }
    }
}

extern "C" void kernel_launch(void* const* d_in, const int* in_sizes, int n_in,
                              void* d_out, int out_size) {
    const float* de   = (const float*)d_in[0];
    const float* mask = (const float*)d_in[1];
    const float* W1   = (const float*)d_in[2];
    const float* b1   = (const float*)d_in[3];
    const float* W2   = (const float*)d_in[4];
    const float* b2   = (const float*)d_in[5];
    const float* W3   = (const float*)d_in[6];
    const float* b3   = (const float*)d_in[7];
    float* out = (float*)d_out;

    prep_zero_kernel<<<188, 256>>>(W2, W3, (float4*)out);

    const int smem_bytes = SW_TOT * 4;  // 40512
    cudaFuncSetAttribute(fused_sensor_kernel,
                         cudaFuncAttributeMaxDynamicSharedMemorySize, smem_bytes);

    fused_sensor_kernel<<<NE / EB, 128, smem_bytes>>>(   // 1250 CTAs
        de, mask, W1, b1, b2, b3, out);
}

// round 16
// speedup vs baseline: 1.7775x; 1.4202x over previous
#include <cuda_runtime.h>
#include <cuda_fp16.h>
#include <math.h>
#include <stdint.h>

typedef unsigned long long ull;

#define NE 80000
#define TT 2000
#define SS 12
#define HH 128
#define EB 64                      // electrons per CTA (MMA M)
#define MASK_COEF 1.2615662610f    // GAUSS_NORM / sqrt(0.1)

// smem word offsets
#define SW_AHI  0                  // 64 x 68 fp16x2 k-pairs (padded stride 68)
#define SW_B2   (SW_AHI + EB*68)   // 4352
#define SW_B3   (SW_B2 + HH)       // 4480 (+16)
#define SW_RESP (SW_B3 + 16)       // 4496: 64 x 12 f32
#define SW_W1   (SW_RESP + EB*SS)  // 5264: W1 (3x128) + b1 (128)
#define SW_RED  (SW_W1 + 512)      // 5776: [wid(4)][lane(32)][16] f32
#define SW_TOT  (SW_RED + 4*32*16) // 7824 words = 31296 B

// W2 fp16 fragments: [kk(8)][npair(8)][lane(32)] -> ulonglong2 (nt even, nt odd)
__device__ ulonglong2 g_BfragH[8 * 8 * 32];
// W3 fp16 fragments: [kk(8)][lane(32)] -> ulonglong2 (nt0, nt1)
__device__ ulonglong2 g_W3fragH[8 * 32];

__device__ __forceinline__ uint32_t hfpack(float a, float b) {
    __half2 t = __floats2half2_rn(a, b);   // .x = low half
    return *(uint32_t*)&t;
}
__device__ __forceinline__ uint32_t smem_u32(const void* p) {
    uint32_t a;
    asm("{ .reg .u64 t; cvta.to.shared.u64 t, %1; cvt.u32.u64 %0, t; }" : "=r"(a) : "l"(p));
    return a;
}
__device__ __forceinline__ void ldsm4(uint32_t* r, uint32_t addr) {
    asm volatile("ldmatrix.sync.aligned.m8n8.x4.shared.b16 {%0,%1,%2,%3}, [%4];"
        : "=r"(r[0]), "=r"(r[1]), "=r"(r[2]), "=r"(r[3]) : "r"(addr));
}
__device__ __forceinline__ void mmaH(float* c, const uint32_t* a, uint32_t b0, uint32_t b1) {
    asm volatile(
        "mma.sync.aligned.m16n8k16.row.col.f32.f16.f16.f32 "
        "{%0,%1,%2,%3}, {%4,%5,%6,%7}, {%8,%9}, {%0,%1,%2,%3};"
        : "+f"(c[0]), "+f"(c[1]), "+f"(c[2]), "+f"(c[3])
        : "r"(a[0]), "r"(a[1]), "r"(a[2]), "r"(a[3]), "r"(b0), "r"(b1));
}
__device__ __forceinline__ void mma_u(float* c, const uint32_t* a, ull b) {
    mmaH(c, a, (uint32_t)b, (uint32_t)(b >> 32));
}

// one launch: zero output + pack W2/W3 fp16 fragments
// (fragment index decode identical to the R11-validated prep; fp16, single level)
__global__ void prep_zero_kernel(const float* __restrict__ W2,
                                 const float* __restrict__ W3,
                                 float4* __restrict__ out4) {
    int idx = blockIdx.x * 256 + threadIdx.x;
    if (idx < 48000) out4[idx] = make_float4(0.f, 0.f, 0.f, 0.f);

    if (idx < 4096) {              // W2 fragments
        int lane  = idx & 31;
        int ntile = (idx >> 5) & 15;
        int kk    = (idx >> 9) & 7;
        int kp0 = kk * 8 + (lane & 3);
        int n   = ntile * 8 + (lane >> 2);
        uint32_t b0 = hfpack(W2[(2 * kp0) * HH + n],       W2[(2 * kp0 + 1) * HH + n]);
        uint32_t b1 = hfpack(W2[(2 * (kp0 + 4)) * HH + n], W2[(2 * (kp0 + 4) + 1) * HH + n]);
        ull v = ((ull)b1 << 32) | (ull)b0;
        int base = (kk * 8 + (ntile >> 1)) * 32 + lane;
        if (ntile & 1) g_BfragH[base].y = v; else g_BfragH[base].x = v;
    } else if (idx < 4096 + 512) { // W3 fragments (N=16: sensors 0..11 + zero pad)
        int t = idx - 4096;
        int lane = t & 31;
        int nt   = (t >> 5) & 1;
        int kk   = (t >> 6) & 7;
        int kp0 = kk * 8 + (lane & 3);
        int n   = nt * 8 + (lane >> 2);
        float v0 = 0.f, v1 = 0.f, w0 = 0.f, w1 = 0.f;
        if (n < SS) {
            v0 = W3[(2 * kp0) * SS + n];
            v1 = W3[(2 * kp0 + 1) * SS + n];
            w0 = W3[(2 * (kp0 + 4)) * SS + n];
            w1 = W3[(2 * (kp0 + 4) + 1) * SS + n];
        }
        ull v = ((ull)hfpack(w0, w1) << 32) | (ull)hfpack(v0, v1);
        int base = kk * 32 + lane;
        if (nt) g_W3fragH[base].y = v; else g_W3fragH[base].x = v;
    }
}

__global__ __launch_bounds__(128, 4)
void fused_sensor_kernel(
    const float* __restrict__ de,    // (B,N,3)
    const float* __restrict__ mask,  // (B,N)
    const float* __restrict__ W1,    // (3,H)
    const float* __restrict__ b1,    // (H)
    const float* __restrict__ b2,    // (H)
    const float* __restrict__ b3,    // (S)
    float* __restrict__ out)         // (B,S,T)
{
    extern __shared__ uint32_t smw[];
    float* smf = (float*)smw;
    const uint32_t smb = smem_u32(smw);
    const int tid  = threadIdx.x;
    const int lane = tid & 31;
    const int wid  = tid >> 5;

    // ---- stage small weights to smem ----
    for (int i = tid; i < 3 * HH; i += 128) smf[SW_W1 + i] = W1[i];
    if (tid < HH) {
        smf[SW_W1 + 384 + tid] = b1[tid];
        smf[SW_B2 + tid] = b2[tid];
    }
    if (tid < SS) smf[SW_B3 + tid] = b3[tid];

    // electron inputs (2 threads/electron)
    const int el = tid >> 1;
    const int q  = tid & 1;
    const int eg = blockIdx.x * EB + el;
    const float x0 = de[3 * eg + 0];
    const float x1 = de[3 * eg + 1];
    const float x2 = de[3 * eg + 2];
    const float msk = mask[eg];
    __syncthreads();

    // ---- layer 1 -> A (fp16, no split) via smem-broadcast LDS.128 ----
#pragma unroll 4
    for (int i4 = 0; i4 < 16; ++i4) {
        int k = q * 64 + i4 * 4;
        float4 wa = *(const float4*)&smf[SW_W1 + k];
        float4 wb = *(const float4*)&smf[SW_W1 + 128 + k];
        float4 wc = *(const float4*)&smf[SW_W1 + 256 + k];
        float4 bb = *(const float4*)&smf[SW_W1 + 384 + k];
        float v0 = fmaxf(fmaf(x2, wc.x, fmaf(x1, wb.x, fmaf(x0, wa.x, bb.x))), 0.f);
        float v1 = fmaxf(fmaf(x2, wc.y, fmaf(x1, wb.y, fmaf(x0, wa.y, bb.y))), 0.f);
        float v2 = fmaxf(fmaf(x2, wc.z, fmaf(x1, wb.z, fmaf(x0, wa.z, bb.z))), 0.f);
        float v3 = fmaxf(fmaf(x2, wc.w, fmaf(x1, wb.w, fmaf(x0, wa.w, bb.w))), 0.f);
        int kp = k >> 1;
        smw[SW_AHI + el * 68 + kp]     = hfpack(v0, v1);
        smw[SW_AHI + el * 68 + kp + 1] = hfpack(v2, v3);
    }
    __syncthreads();

    // ---- layer-2 GEMM (single fp16 pass): warp (mw,nw) = 32 rows x 64 cols ----
    const int mw = wid & 1, nw = wid >> 1;
    const int m0 = mw * 32;
    float acc[2][8][4];
#pragma unroll
    for (int mt = 0; mt < 2; ++mt)
#pragma unroll
        for (int nt = 0; nt < 8; ++nt)
#pragma unroll
            for (int c = 0; c < 4; ++c) acc[mt][nt][c] = 0.0f;

    const uint32_t aoff = ((m0 + (lane & 7) + ((lane >> 3) & 1) * 8) * 68 + (lane >> 4) * 4) * 4;
    {
        const uint32_t Ab = smb + aoff;
        const ulonglong2* Bp = g_BfragH + nw * 4 * 32 + lane;
#pragma unroll
        for (int kk = 0; kk < 8; ++kk) {
            uint32_t af[2][4];
            ldsm4(af[0], Ab + kk * 32);
            ldsm4(af[1], Ab + 16 * 68 * 4 + kk * 32);
            const ulonglong2* Bk = Bp + kk * 256;
            ulonglong2 u0 = Bk[0], u1 = Bk[32], u2 = Bk[64], u3 = Bk[96];  // 4x LDG.128
#pragma unroll
            for (int mt = 0; mt < 2; ++mt) {
                mma_u(acc[mt][0], af[mt], u0.x);
                mma_u(acc[mt][1], af[mt], u0.y);
                mma_u(acc[mt][2], af[mt], u1.x);
                mma_u(acc[mt][3], af[mt], u1.y);
                mma_u(acc[mt][4], af[mt], u2.x);
                mma_u(acc[mt][5], af[mt], u2.y);
                mma_u(acc[mt][6], af[mt], u3.x);
                mma_u(acc[mt][7], af[mt], u3.y);
            }
        }
    }

    // ---- layer-3 straight from registers: C-frag(m16n8 pair) == A-frag(m16k16) ----
    // h2 = relu(acc + b2) packed to fp16 in-register; partial over this warp's 64 k.
    float acc3[2][2][4];
#pragma unroll
    for (int mt = 0; mt < 2; ++mt)
#pragma unroll
        for (int nt = 0; nt < 2; ++nt)
#pragma unroll
            for (int c = 0; c < 4; ++c) acc3[mt][nt][c] = 0.0f;

    const int c2 = lane & 3;
#pragma unroll
    for (int kf = 0; kf < 4; ++kf) {
        int j0 = nw * 64 + kf * 16 + 2 * c2;      // even -> float2-aligned
        float2 bA = *(const float2*)&smf[SW_B2 + j0];
        float2 bB = *(const float2*)&smf[SW_B2 + j0 + 8];
        ulonglong2 f = g_W3fragH[(nw * 4 + kf) * 32 + lane];
#pragma unroll
        for (int mt = 0; mt < 2; ++mt) {
            uint32_t a3[4];
            a3[0] = hfpack(fmaxf(acc[mt][2*kf][0]   + bA.x, 0.f), fmaxf(acc[mt][2*kf][1]   + bA.y, 0.f));
            a3[1] = hfpack(fmaxf(acc[mt][2*kf][2]   + bA.x, 0.f), fmaxf(acc[mt][2*kf][3]   + bA.y, 0.f));
            a3[2] = hfpack(fmaxf(acc[mt][2*kf+1][0] + bB.x, 0.f), fmaxf(acc[mt][2*kf+1][1] + bB.y, 0.f));
            a3[3] = hfpack(fmaxf(acc[mt][2*kf+1][2] + bB.x, 0.f), fmaxf(acc[mt][2*kf+1][3] + bB.y, 0.f));
            mma_u(acc3[mt][0], a3, f.x);
            mma_u(acc3[mt][1], a3, f.y);
        }
    }

    // ---- cross-warp k-reduction (nw=0 partial + nw=1 partial), resp -> smem ----
    {
        float4* red = (float4*)&smf[SW_RED + (wid * 32 + lane) * 16];
#pragma unroll
        for (int mt = 0; mt < 2; ++mt)
#pragma unroll
            for (int nt = 0; nt < 2; ++nt)
                red[mt * 2 + nt] = make_float4(acc3[mt][nt][0], acc3[mt][nt][1],
                                               acc3[mt][nt][2], acc3[mt][nt][3]);
    }
    __syncthreads();
    if (wid >= 2) {   // nw=1 warps finalize rows mw*32..+32
        const float4* peer = (const float4*)&smf[SW_RED + ((wid - 2) * 32 + lane) * 16];
        const int r = lane >> 2;
#pragma unroll
        for (int mt = 0; mt < 2; ++mt)
#pragma unroll
            for (int nt = 0; nt < 2; ++nt) {
                float4 p = peer[mt * 2 + nt];
                float s0 = acc3[mt][nt][0] + p.x;
                float s1 = acc3[mt][nt][1] + p.y;
                float s2 = acc3[mt][nt][2] + p.z;
                float s3 = acc3[mt][nt][3] + p.w;
                int j = nt * 8 + 2 * c2;
                if (j < SS) {
                    int row0 = m0 + mt * 16 + r;
                    *(float2*)&smf[SW_RESP + row0 * SS + j] = make_float2(s0, s1);
                    *(float2*)&smf[SW_RESP + (row0 + 8) * SS + j] = make_float2(s2, s3);
                }
            }
    }
    __syncthreads();

    // ---- sparse Gaussian scatter (exp(-5d^2) < 3e-20 beyond |d|=3) ----
    {
        float resp[SS];
#pragma unroll
        for (int s = 0; s < SS; ++s)
            resp[s] = smf[SW_RESP + el * SS + s] + smf[SW_B3 + s];

        const float z = x2;
        const float c = msk * MASK_COEF;
        int t0 = (int)ceilf(z - 3.0f);
        int t1 = (int)floorf(z + 3.0f);
        if (t0 < 0) t0 = 0;
        if (t1 > TT - 1) t1 = TT - 1;
        const int b = eg / 10000;
        float* ob = out + (size_t)b * SS * TT;
        for (int t = t0 + q; t <= t1; t += 2) {
            float d = (float)t - z;
            float w = __expf(-5.0f * d * d) * c;
#pragma unroll
            for (int s = 0; s < SS; ++s)
                atomicAdd(&ob[s * TT + t], w * resp[s]);
        }
    }
}

extern "C" void kernel_launch(void* const* d_in, const int* in_sizes, int n_in,
                              void* d_out, int out_size) {
    const float* de   = (const float*)d_in[0];
    const float* mask = (const float*)d_in[1];
    const float* W1   = (const float*)d_in[2];
    const float* b1   = (const float*)d_in[3];
    const float* W2   = (const float*)d_in[4];
    const float* b2   = (const float*)d_in[5];
    const float* W3   = (const float*)d_in[6];
    const float* b3   = (const float*)d_in[7];
    float* out = (float*)d_out;

    prep_zero_kernel<<<188, 256>>>(W2, W3, (float4*)out);

    const int smem_bytes = SW_TOT * 4;  // 31296
    cudaFuncSetAttribute(fused_sensor_kernel,
                         cudaFuncAttributeMaxDynamicSharedMemorySize, smem_bytes);

    fused_sensor_kernel<<<NE / EB, 128, smem_bytes>>>(   // 1250 CTAs
        de, mask, W1, b1, b2, b3, out);
}

// round 17
// speedup vs baseline: 1.9542x; 1.0994x over previous
#include <cuda_runtime.h>
#include <cuda_fp16.h>
#include <math.h>
#include <stdint.h>

typedef unsigned long long ull;

#define NE 80000
#define TT 2000
#define SS 12
#define HH 128
#define EB 64                      // electrons per CTA
#define MASK_COEF 1.2615662610f    // GAUSS_NORM / sqrt(0.1)

// smem word offsets (tiny now: no A buffer, no reduce buffer)
#define SW_DE   0                  // 64 x 3 floats
#define SW_MASK (SW_DE + 192)      // 64
#define SW_B1   (SW_MASK + 64)     // 128
#define SW_B2   (SW_B1 + 128)      // 128
#define SW_B3   (SW_B2 + 128)      // 16
#define SW_RESP (SW_B3 + 16)       // 64 x 12 f32
#define SW_TOT  (SW_RESP + EB*SS)  // 1296 words = 5184 B

// W2 fp16 fragments: [kk(8)][npair(8)][lane(32)] -> ulonglong2 (nt even, nt odd)
__device__ ulonglong2 g_BfragH[8 * 8 * 32];
// W3 fp16 fragments: [kk(8)][lane(32)] -> ulonglong2 (nt0, nt1)
__device__ ulonglong2 g_W3fragH[8 * 32];
// W1 fp16 fragments (K=16, only k<3 nonzero): [sp(2)][quad(4)][lane(32)][comp(4)]
// comp = nt&3, quad = nt>>2; sp0 = hi, sp1 = lo residual
__device__ uint32_t g_W1fragU[2 * 4 * 32 * 4];

__device__ __forceinline__ uint32_t hfpack(float a, float b) {
    __half2 t = __floats2half2_rn(a, b);   // .x = low half
    return *(uint32_t*)&t;
}
__device__ __forceinline__ void mmaH(float* c, const uint32_t* a, uint32_t b0, uint32_t b1) {
    asm volatile(
        "mma.sync.aligned.m16n8k16.row.col.f32.f16.f16.f32 "
        "{%0,%1,%2,%3}, {%4,%5,%6,%7}, {%8,%9}, {%0,%1,%2,%3};"
        : "+f"(c[0]), "+f"(c[1]), "+f"(c[2]), "+f"(c[3])
        : "r"(a[0]), "r"(a[1]), "r"(a[2]), "r"(a[3]), "r"(b0), "r"(b1));
}
__device__ __forceinline__ void mma_u(float* c, const uint32_t* a, ull b) {
    mmaH(c, a, (uint32_t)b, (uint32_t)(b >> 32));
}
__device__ __forceinline__ float f16res(float v) {   // v - fp16(v)
    return v - __half2float(__float2half_rn(v));
}

// one launch: zero output + pack W2/W3/W1 fp16 fragments
__global__ void prep_zero_kernel(const float* __restrict__ W1,
                                 const float* __restrict__ W2,
                                 const float* __restrict__ W3,
                                 float4* __restrict__ out4) {
    int idx = blockIdx.x * 256 + threadIdx.x;
    if (idx < 48000) out4[idx] = make_float4(0.f, 0.f, 0.f, 0.f);

    if (idx < 4096) {              // W2 fragments (R16-validated)
        int lane  = idx & 31;
        int ntile = (idx >> 5) & 15;
        int kk    = (idx >> 9) & 7;
        int kp0 = kk * 8 + (lane & 3);
        int n   = ntile * 8 + (lane >> 2);
        uint32_t b0 = hfpack(W2[(2 * kp0) * HH + n],       W2[(2 * kp0 + 1) * HH + n]);
        uint32_t b1 = hfpack(W2[(2 * (kp0 + 4)) * HH + n], W2[(2 * (kp0 + 4) + 1) * HH + n]);
        ull v = ((ull)b1 << 32) | (ull)b0;
        int base = (kk * 8 + (ntile >> 1)) * 32 + lane;
        if (ntile & 1) g_BfragH[base].y = v; else g_BfragH[base].x = v;
    } else if (idx < 4096 + 512) { // W3 fragments (N=16: sensors 0..11 + zero pad)
        int t = idx - 4096;
        int lane = t & 31;
        int nt   = (t >> 5) & 1;
        int kk   = (t >> 6) & 7;
        int kp0 = kk * 8 + (lane & 3);
        int n   = nt * 8 + (lane >> 2);
        float v0 = 0.f, v1 = 0.f, w0 = 0.f, w1 = 0.f;
        if (n < SS) {
            v0 = W3[(2 * kp0) * SS + n];
            v1 = W3[(2 * kp0 + 1) * SS + n];
            w0 = W3[(2 * (kp0 + 4)) * SS + n];
            w1 = W3[(2 * (kp0 + 4) + 1) * SS + n];
        }
        ull v = ((ull)hfpack(w0, w1) << 32) | (ull)hfpack(v0, v1);
        int base = kk * 32 + lane;
        if (nt) g_W3fragH[base].y = v; else g_W3fragH[base].x = v;
    } else if (idx < 4608 + 1024) { // W1 fragments: kk=0 (K=16), rows k=0..2 live
        int t = idx - 4608;
        int lane = t & 31;
        int nt   = (t >> 5) & 15;
        int sp   = t >> 9;
        int c2 = lane & 3;
        int n  = nt * 8 + (lane >> 2);
        float u0 = 0.f, u1 = 0.f;
        if (c2 == 0)      { u0 = W1[n];           u1 = W1[HH + n]; }
        else if (c2 == 1) { u0 = W1[2 * HH + n];  u1 = 0.f; }
        uint32_t b = (sp == 0) ? hfpack(u0, u1)
                               : hfpack(f16res(u0), f16res(u1));
        g_W1fragU[((sp * 4 + (nt >> 2)) * 32 + lane) * 4 + (nt & 3)] = b;
    }
}

__global__ __launch_bounds__(128, 4)
void fused_sensor_kernel(
    const float* __restrict__ de,    // (B,N,3)
    const float* __restrict__ mask,  // (B,N)
    const float* __restrict__ b1,    // (H)
    const float* __restrict__ b2,    // (H)
    const float* __restrict__ b3,    // (S)
    float* __restrict__ out)         // (B,S,T)
{
    extern __shared__ float smf[];
    const int tid  = threadIdx.x;
    const int lane = tid & 31;
    const int wid  = tid >> 5;
    const int r  = lane >> 2;
    const int c2 = lane & 3;

    // ---- stage de/mask/biases to smem ----
    for (int i = tid; i < 192; i += 128) smf[SW_DE + i] = de[blockIdx.x * 192 + i];
    if (tid < EB) smf[SW_MASK + tid] = mask[blockIdx.x * EB + tid];
    if (tid < HH) { smf[SW_B1 + tid] = b1[tid]; smf[SW_B2 + tid] = b2[tid]; }
    if (tid < SS) smf[SW_B3 + tid] = b3[tid];
    __syncthreads();

    // ---- build layer-1 A fragments (warp owns electrons 16*wid .. +16) ----
    // a0: row r, k=2c2..2c2+1 ; a1: row r+8 ; a2=a3=0 (k 8..15 zero-padded)
    uint32_t aH[4], aL[4];
    {
        const int er  = wid * 16 + r;
        const int er8 = er + 8;
        float p0, p1, q0, q1;
        if (c2 == 0)      { p0 = smf[SW_DE + er * 3];     p1 = smf[SW_DE + er * 3 + 1];
                            q0 = smf[SW_DE + er8 * 3];    q1 = smf[SW_DE + er8 * 3 + 1]; }
        else if (c2 == 1) { p0 = smf[SW_DE + er * 3 + 2]; p1 = 0.f;
                            q0 = smf[SW_DE + er8 * 3 + 2]; q1 = 0.f; }
        else              { p0 = p1 = q0 = q1 = 0.f; }
        aH[0] = hfpack(p0, p1);          aH[1] = hfpack(q0, q1);
        aL[0] = hfpack(f16res(p0), f16res(p1));
        aL[1] = hfpack(f16res(q0), f16res(q1));
        aH[2] = aH[3] = aL[2] = aL[3] = 0u;
    }

    // ---- layer-1 MMA: 3-pass split-fp16 (h1 fp32-exact), 16 ntiles ----
    float accL1[16][4];
#pragma unroll
    for (int nt = 0; nt < 16; ++nt)
#pragma unroll
        for (int c = 0; c < 4; ++c) accL1[nt][c] = 0.f;
    {
        const uint4* W1q = (const uint4*)g_W1fragU;
        uint4 WH[4], WL[4];
#pragma unroll
        for (int qd = 0; qd < 4; ++qd) {
            WH[qd] = W1q[qd * 32 + lane];
            WL[qd] = W1q[(4 + qd) * 32 + lane];
        }
#pragma unroll
        for (int nt = 0; nt < 16; ++nt) {
            const uint4 h = WH[nt >> 2], l = WL[nt >> 2];
            uint32_t bh = (nt & 2) ? ((nt & 1) ? h.w : h.z) : ((nt & 1) ? h.y : h.x);
            uint32_t bl = (nt & 2) ? ((nt & 1) ? l.w : l.z) : ((nt & 1) ? l.y : l.x);
            mmaH(accL1[nt], aH, bh, 0u);
            mmaH(accL1[nt], aL, bh, 0u);
            mmaH(accL1[nt], aH, bl, 0u);
        }
    }

    // ---- h1 = relu(accL1 + b1) -> fp16 A-fragments for layer 2 (in registers) ----
    uint32_t A2[8][4];
#pragma unroll
    for (int kk = 0; kk < 8; ++kk) {
        int j0 = kk * 16 + 2 * c2;
        float2 bA = *(const float2*)&smf[SW_B1 + j0];
        float2 bB = *(const float2*)&smf[SW_B1 + j0 + 8];
        A2[kk][0] = hfpack(fmaxf(accL1[2*kk][0]   + bA.x, 0.f), fmaxf(accL1[2*kk][1]   + bA.y, 0.f));
        A2[kk][1] = hfpack(fmaxf(accL1[2*kk][2]   + bA.x, 0.f), fmaxf(accL1[2*kk][3]   + bA.y, 0.f));
        A2[kk][2] = hfpack(fmaxf(accL1[2*kk+1][0] + bB.x, 0.f), fmaxf(accL1[2*kk+1][1] + bB.y, 0.f));
        A2[kk][3] = hfpack(fmaxf(accL1[2*kk+1][2] + bB.x, 0.f), fmaxf(accL1[2*kk+1][3] + bB.y, 0.f));
    }

    // ---- layer-2 MMA: M=16 (this warp's electrons) x N=128, K=128 ----
    float acc2[16][4];
#pragma unroll
    for (int nt = 0; nt < 16; ++nt)
#pragma unroll
        for (int c = 0; c < 4; ++c) acc2[nt][c] = 0.f;
#pragma unroll
    for (int kk = 0; kk < 8; ++kk) {
        const ulonglong2* Bk = g_BfragH + kk * 256 + lane;
#pragma unroll
        for (int p = 0; p < 8; ++p) {
            ulonglong2 u = Bk[p * 32];           // LDG.128, L1-hot
            mma_u(acc2[2*p],     A2[kk], u.x);
            mma_u(acc2[2*p + 1], A2[kk], u.y);
        }
    }

    // ---- layer-3 from registers: h2 = relu(acc2 + b2) -> fp16 -> MMA with W3 ----
    float acc3[2][4];
#pragma unroll
    for (int nt = 0; nt < 2; ++nt)
#pragma unroll
        for (int c = 0; c < 4; ++c) acc3[nt][c] = 0.f;
#pragma unroll
    for (int kf = 0; kf < 8; ++kf) {
        int j0 = kf * 16 + 2 * c2;
        float2 bA = *(const float2*)&smf[SW_B2 + j0];
        float2 bB = *(const float2*)&smf[SW_B2 + j0 + 8];
        uint32_t a3[4];
        a3[0] = hfpack(fmaxf(acc2[2*kf][0]   + bA.x, 0.f), fmaxf(acc2[2*kf][1]   + bA.y, 0.f));
        a3[1] = hfpack(fmaxf(acc2[2*kf][2]   + bA.x, 0.f), fmaxf(acc2[2*kf][3]   + bA.y, 0.f));
        a3[2] = hfpack(fmaxf(acc2[2*kf+1][0] + bB.x, 0.f), fmaxf(acc2[2*kf+1][1] + bB.y, 0.f));
        a3[3] = hfpack(fmaxf(acc2[2*kf+1][2] + bB.x, 0.f), fmaxf(acc2[2*kf+1][3] + bB.y, 0.f));
        ulonglong2 f = g_W3fragH[kf * 32 + lane];
        mma_u(acc3[0], a3, f.x);
        mma_u(acc3[1], a3, f.y);
    }

    // ---- resp -> smem (rows = electrons, cols = sensors); no cross-warp reduce ----
#pragma unroll
    for (int nt = 0; nt < 2; ++nt) {
        int j = nt * 8 + 2 * c2;
        if (j < SS) {
            int row0 = wid * 16 + r;
            *(float2*)&smf[SW_RESP + row0 * SS + j]       = make_float2(acc3[nt][0], acc3[nt][1]);
            *(float2*)&smf[SW_RESP + (row0 + 8) * SS + j] = make_float2(acc3[nt][2], acc3[nt][3]);
        }
    }
    __syncthreads();

    // ---- sparse Gaussian scatter (exp(-5d^2) < 3e-20 beyond |d|=3) ----
    {
        const int el = tid >> 1;
        const int q  = tid & 1;
        float resp[SS];
#pragma unroll
        for (int s = 0; s < SS; ++s)
            resp[s] = smf[SW_RESP + el * SS + s] + smf[SW_B3 + s];

        const float z = smf[SW_DE + el * 3 + 2];
        const float c = smf[SW_MASK + el] * MASK_COEF;
        int t0 = (int)ceilf(z - 3.0f);
        int t1 = (int)floorf(z + 3.0f);
        if (t0 < 0) t0 = 0;
        if (t1 > TT - 1) t1 = TT - 1;
        const int eg = blockIdx.x * EB + el;
        const int b = eg / 10000;
        float* ob = out + (size_t)b * SS * TT;
        for (int t = t0 + q; t <= t1; t += 2) {
            float d = (float)t - z;
            float w = __expf(-5.0f * d * d) * c;
#pragma unroll
            for (int s = 0; s < SS; ++s)
                atomicAdd(&ob[s * TT + t], w * resp[s]);
        }
    }
}

extern "C" void kernel_launch(void* const* d_in, const int* in_sizes, int n_in,
                              void* d_out, int out_size) {
    const float* de   = (const float*)d_in[0];
    const float* mask = (const float*)d_in[1];
    const float* W1   = (const float*)d_in[2];
    const float* b1   = (const float*)d_in[3];
    const float* W2   = (const float*)d_in[4];
    const float* b2   = (const float*)d_in[5];
    const float* W3   = (const float*)d_in[6];
    const float* b3   = (const float*)d_in[7];
    float* out = (float*)d_out;

    prep_zero_kernel<<<188, 256>>>(W1, W2, W3, (float4*)out);

    const int smem_bytes = SW_TOT * 4;  // 5184
    cudaFuncSetAttribute(fused_sensor_kernel,
                         cudaFuncAttributeMaxDynamicSharedMemorySize, smem_bytes);

    fused_sensor_kernel<<<NE / EB, 128, smem_bytes>>>(   // 1250 CTAs
        de, mask, b1, b2, b3, out);
}